// round 3
// baseline (speedup 1.0000x reference)
#include <cuda_runtime.h>

#define B_   1024
#define T_   128
#define H_   512
#define NG_  2048

// ---------------- static scratch (no allocations allowed) ----------------
__device__ float g_W1T[1024 * 512];      // [k][i]  (k over [h|c])
__device__ float g_W3T[1024 * 512];      // [k][i]  (k over [z1|z2])
__device__ float g_WgT[1024 * 2048];     // [k][p]  k over [x|h], p = 4*i+q gate-interleaved
__device__ float g_bgp[2048];            // bih+bhh, gate-interleaved
__device__ float g_z2[T_ * B_ * H_];     // precomputed relu(v_t @ W2^T + b2), [t][b][i]
__device__ float g_z1[B_ * H_];
__device__ float g_x [B_ * H_];
__device__ float g_h [2][B_ * H_];       // ping-pong (K3 reads h as GEMM operand while writing h_new)
__device__ float g_c [B_ * H_];

// ---------------- f32x2 packed-FMA helpers (Blackwell FFMA2) ----------------
__device__ __forceinline__ unsigned long long dup2(float a) {
    unsigned long long r;
    asm("mov.b64 %0, {%1, %1};" : "=l"(r) : "f"(a));
    return r;
}
__device__ __forceinline__ void ffma2(unsigned long long& acc,
                                      unsigned long long a, unsigned long long b) {
    asm("fma.rn.f32x2 %0, %1, %2, %0;" : "+l"(acc) : "l"(a), "l"(b));
}
__device__ __forceinline__ float2 unpack2(unsigned long long v) {
    float2 r;
    asm("mov.b64 {%0, %1}, %2;" : "=f"(r.x), "=f"(r.y) : "l"(v));
    return r;
}

// ---------------- prep: transposes, gate interleave, zero state ----------------
__global__ __launch_bounds__(256) void prep_weights(
    const float* __restrict__ W1, const float* __restrict__ W3,
    const float* __restrict__ Wih, const float* __restrict__ Whh,
    const float* __restrict__ bih, const float* __restrict__ bhh)
{
    const int N1 = 1024 * 512;
    const int N2 = N1 + 1024 * 512;
    const int N3 = N2 + 1024 * 2048;
    const int N4 = N3 + 2048;
    const int N5 = N4 + B_ * H_;   // zero g_h[0]
    const int N6 = N5 + B_ * H_;   // zero g_c
    for (int idx = blockIdx.x * blockDim.x + threadIdx.x; idx < N6;
         idx += gridDim.x * blockDim.x) {
        if (idx < N1) {
            int k = idx >> 9, i = idx & 511;
            g_W1T[idx] = W1[i * 1024 + k];
        } else if (idx < N2) {
            int j = idx - N1;
            int k = j >> 9, i = j & 511;
            g_W3T[j] = W3[i * 1024 + k];
        } else if (idx < N3) {
            int j = idx - N2;
            int k = j >> 11, p = j & 2047;
            int i = p >> 2, q = p & 3;
            int r = q * 512 + i;               // PyTorch gate order i,f,g,o
            g_WgT[j] = (k < 512) ? Wih[r * 512 + k] : Whh[r * 512 + (k - 512)];
        } else if (idx < N4) {
            int p = idx - N3;
            int i = p >> 2, q = p & 3;
            int r = q * 512 + i;
            g_bgp[p] = bih[r] + bhh[r];
        } else if (idx < N5) {
            g_h[0][idx - N4] = 0.f;
        } else {
            g_c[idx - N5] = 0.f;
        }
    }
}

// ---------------- prep: z2[t][b][i] = relu(v @ W2^T + b2) for ALL t up front ----------------
__global__ __launch_bounds__(256) void prep_z2(
    const float* __restrict__ sv,   // [B][T][10]
    const float* __restrict__ W2,   // [512][10]
    const float* __restrict__ b2)
{
    __shared__ float W2s[10 * 512];   // transposed: W2s[j][i]
    __shared__ float svs[32 * 10];
    int tid = threadIdx.x;
    for (int idx = tid; idx < 5120; idx += 256) {
        int i = idx / 10, j = idx % 10;
        W2s[j * 512 + i] = W2[idx];
    }
    int u0 = blockIdx.x * 32;   // 32 (b,t) pairs per block, u = b*T + t
    for (int idx = tid; idx < 320; idx += 256) svs[idx] = sv[u0 * 10 + idx];
    __syncthreads();

    int i0 = tid, i1 = tid + 256;
    float bias0 = b2[i0], bias1 = b2[i1];
    for (int p = 0; p < 32; ++p) {
        int u = u0 + p;
        int b = u >> 7, t = u & 127;
        float a0 = bias0, a1 = bias1;
#pragma unroll
        for (int j = 0; j < 10; ++j) {
            float s = svs[p * 10 + j];
            a0 += s * W2s[j * 512 + i0];
            a1 += s * W2s[j * 512 + i1];
        }
        float* dst = g_z2 + (size_t)(t * 1024 + b) * 512;
        dst[i0] = fmaxf(a0, 0.f);
        dst[i1] = fmaxf(a1, 0.f);
    }
}

// ---------------- GEMM 64x64x16, C = relu([A1|A2] @ BT + bias) ----------------
// mode 0: z1 = relu([h_ping | c] @ W1T + b1)      -> g_z1
// mode 1: x  = relu([z1 | z2_t] @ W3T + b3)       -> g_x
__global__ __launch_bounds__(256, 1) void gemm_relu64(
    int mode, int ping, int t, const float* __restrict__ bias)
{
    const float* A1;
    const float* A2;
    const float* BT;
    float* C;
    if (mode == 0) { A1 = g_h[ping]; A2 = g_c;                       BT = g_W1T; C = g_z1; }
    else           { A1 = g_z1;      A2 = g_z2 + (size_t)t * B_ * H_; BT = g_W3T; C = g_x;  }

    __shared__ __align__(16) float As[64 * 20];   // [m][k], pitch 20
    __shared__ __align__(16) float Bs[16 * 64];   // [k][n]

    int tid = threadIdx.x;
    int m0 = blockIdx.x * 64;
    int n0 = blockIdx.y * 64;
    int tm = tid >> 4, tn = tid & 15;

    int am = tid >> 2;          // 0..63
    int ak = (tid & 3) << 2;    // 0,4,8,12
    int bk = tid >> 4;          // 0..15
    int bn = (tid & 15) << 2;   // 0..60

    unsigned long long acc[4][2];
#pragma unroll
    for (int j = 0; j < 4; ++j) { acc[j][0] = 0ULL; acc[j][1] = 0ULL; }

    float4 aR = *(const float4*)(A1 + (m0 + am) * 512 + ak);
    float4 bR = *(const float4*)(BT + bk * 512 + n0 + bn);

    const int KT = 64;   // K = 1024
    for (int kt = 0; kt < KT; ++kt) {
        *(float4*)(&As[am * 20 + ak]) = aR;
        *(float4*)(&Bs[bk * 64 + bn]) = bR;
        __syncthreads();
        if (kt + 1 < KT) {
            int k0n = (kt + 1) * 16;
            const float* Asrc = (k0n < 512) ? A1 : A2;
            int ko = (k0n & 511) + ak;
            aR = *(const float4*)(Asrc + (m0 + am) * 512 + ko);
            bR = *(const float4*)(BT + (k0n + bk) * 512 + n0 + bn);
        }
#pragma unroll
        for (int kk = 0; kk < 16; ++kk) {
            unsigned long long b0 = *(const unsigned long long*)(&Bs[kk * 64 + tn * 4]);
            unsigned long long b1 = *(const unsigned long long*)(&Bs[kk * 64 + tn * 4 + 2]);
#pragma unroll
            for (int j = 0; j < 4; ++j) {
                unsigned long long ad = dup2(As[(tm * 4 + j) * 20 + kk]);
                ffma2(acc[j][0], ad, b0);
                ffma2(acc[j][1], ad, b1);
            }
        }
        __syncthreads();
    }

    float4 bs4 = *(const float4*)(bias + n0 + tn * 4);
#pragma unroll
    for (int j = 0; j < 4; ++j) {
        float2 lo = unpack2(acc[j][0]);
        float2 hi = unpack2(acc[j][1]);
        float4 o;
        o.x = fmaxf(lo.x + bs4.x, 0.f);
        o.y = fmaxf(lo.y + bs4.y, 0.f);
        o.z = fmaxf(hi.x + bs4.z, 0.f);
        o.w = fmaxf(hi.y + bs4.w, 0.f);
        *(float4*)(C + (m0 + tm * 4 + j) * 512 + n0 + tn * 4) = o;
    }
}

// ---------------- GEMM 128x128x16 (gates, gate-interleaved cols) + fused LSTM cell ----------------
__global__ __launch_bounds__(256, 1) void gemm_lstm(
    int ping, int t, float* __restrict__ out)
{
    const float* X   = g_x;
    const float* Hin = g_h[ping];
    float* Hout      = g_h[ping ^ 1];

    __shared__ __align__(16) float As[128 * 20];   // [m][k], pitch 20
    __shared__ __align__(16) float Bs[16 * 128];   // [k][p]

    int tid = threadIdx.x;
    int m0 = blockIdx.x * 128;
    int n0 = blockIdx.y * 128;
    int tm = tid >> 4, tn = tid & 15;

    int am  = tid >> 2;          // 0..63 (+64 second pass)
    int ak  = (tid & 3) << 2;
    int bkk = tid >> 5;          // 0..7  (+8 second pass)
    int bn  = (tid & 31) << 2;   // 0..124

    unsigned long long acc[8][4];
#pragma unroll
    for (int j = 0; j < 8; ++j)
#pragma unroll
        for (int q = 0; q < 4; ++q) acc[j][q] = 0ULL;

    float4 aR0 = *(const float4*)(X + (m0 + am) * 512 + ak);
    float4 aR1 = *(const float4*)(X + (m0 + am + 64) * 512 + ak);
    float4 bR0 = *(const float4*)(g_WgT + (0 + bkk) * 2048 + n0 + bn);
    float4 bR1 = *(const float4*)(g_WgT + (8 + bkk) * 2048 + n0 + bn);

    const int KT = 64;   // K = 1024 over [x|h]
    for (int kt = 0; kt < KT; ++kt) {
        *(float4*)(&As[am * 20 + ak])        = aR0;
        *(float4*)(&As[(am + 64) * 20 + ak]) = aR1;
        *(float4*)(&Bs[bkk * 128 + bn])       = bR0;
        *(float4*)(&Bs[(bkk + 8) * 128 + bn]) = bR1;
        __syncthreads();
        if (kt + 1 < KT) {
            int k0n = (kt + 1) * 16;
            const float* Asrc = (k0n < 512) ? X : Hin;
            int ko = (k0n & 511) + ak;
            aR0 = *(const float4*)(Asrc + (m0 + am) * 512 + ko);
            aR1 = *(const float4*)(Asrc + (m0 + am + 64) * 512 + ko);
            bR0 = *(const float4*)(g_WgT + (k0n + bkk) * 2048 + n0 + bn);
            bR1 = *(const float4*)(g_WgT + (k0n + 8 + bkk) * 2048 + n0 + bn);
        }
#pragma unroll
        for (int kk = 0; kk < 16; ++kk) {
            ulonglong2 bp0 = *(const ulonglong2*)(&Bs[kk * 128 + tn * 8]);
            ulonglong2 bp1 = *(const ulonglong2*)(&Bs[kk * 128 + tn * 8 + 4]);
#pragma unroll
            for (int j = 0; j < 8; ++j) {
                unsigned long long ad = dup2(As[(tm * 8 + j) * 20 + kk]);
                ffma2(acc[j][0], ad, bp0.x);
                ffma2(acc[j][1], ad, bp0.y);
                ffma2(acc[j][2], ad, bp1.x);
                ffma2(acc[j][3], ad, bp1.y);
            }
        }
        __syncthreads();
    }

    // ---- fused LSTM pointwise: thread owns 8 batches x 2 units (all 4 gates local) ----
    int ng = n0 + tn * 8;          // interleaved gate-col base (multiple of 8)
    int i0 = ng >> 2;              // hidden unit index base
    float bb[8];
#pragma unroll
    for (int q = 0; q < 8; ++q) bb[q] = g_bgp[ng + q];

#pragma unroll
    for (int j = 0; j < 8; ++j) {
        int b = m0 + tm * 8 + j;
        float2 p0 = unpack2(acc[j][0]);
        float2 p1 = unpack2(acc[j][1]);
        float2 p2 = unpack2(acc[j][2]);
        float2 p3 = unpack2(acc[j][3]);
        float gv[8] = { p0.x, p0.y, p1.x, p1.y, p2.x, p2.y, p3.x, p3.y };
#pragma unroll
        for (int q = 0; q < 2; ++q) {
            int i = i0 + q;
            float ig = gv[q * 4 + 0] + bb[q * 4 + 0];
            float fg = gv[q * 4 + 1] + bb[q * 4 + 1];
            float gg = gv[q * 4 + 2] + bb[q * 4 + 2];
            float og = gv[q * 4 + 3] + bb[q * 4 + 3];
            float is = 1.f / (1.f + expf(-ig));
            float fs = 1.f / (1.f + expf(-fg));
            float gt = tanhf(gg);
            float os = 1.f / (1.f + expf(-og));
            float cold = g_c[b * 512 + i];
            float cn = fs * cold + is * gt;
            float hn = os * tanhf(cn);
            g_c[b * 512 + i]  = cn;
            Hout[b * 512 + i] = hn;
            out[(size_t)(b * T_ + t) * 512 + i] = hn;
        }
    }
}

// ---------------- launch ----------------
extern "C" void kernel_launch(void* const* d_in, const int* in_sizes, int n_in,
                              void* d_out, int out_size)
{
    const float* sv  = (const float*)d_in[0];
    const float* W1  = (const float*)d_in[1];
    const float* b1  = (const float*)d_in[2];
    const float* W2  = (const float*)d_in[3];
    const float* b2  = (const float*)d_in[4];
    const float* W3  = (const float*)d_in[5];
    const float* b3  = (const float*)d_in[6];
    const float* Wih = (const float*)d_in[7];
    const float* Whh = (const float*)d_in[8];
    const float* bih = (const float*)d_in[9];
    const float* bhh = (const float*)d_in[10];
    float* out = (float*)d_out;

    prep_weights<<<4096, 256>>>(W1, W3, Wih, Whh, bih, bhh);
    prep_z2<<<(B_ * T_) / 32, 256>>>(sv, W2, b2);

    dim3 g1(16, 8);    // 1024/64 x 512/64   = 128 blocks
    dim3 g3(8, 16);    // 1024/128 x 2048/128 = 128 blocks
    for (int t = 0; t < T_; ++t) {
        int ping = t & 1;
        gemm_relu64<<<g1, 256>>>(0, ping, t, b1);
        gemm_relu64<<<g1, 256>>>(1, ping, t, b3);
        gemm_lstm<<<g3, 256>>>(ping, t, out);
    }
}

// round 5
// speedup vs baseline: 2.2366x; 2.2366x over previous
#include <cuda_runtime.h>
#include <cuda_bf16.h>
#include <cstdint>

#define B_ 1024
#define T_ 128

typedef unsigned short u16;
typedef uint32_t u32;

// ---------------- static device buffers (plain row-major, k-contiguous) ----------------
__device__ __align__(16) u16 W1hi[512 * 1024], W1lo[512 * 1024];   // [n][k]
__device__ __align__(16) u16 W3hi[512 * 1024], W3lo[512 * 1024];
__device__ __align__(16) u16 Wghi[2048 * 1024], Wglo[2048 * 1024]; // [p=4i+q][k over x|h]
__device__ __align__(16) u16 Hhi[2][B_ * 512], Hlo[2][B_ * 512];
__device__ __align__(16) u16 Chi[B_ * 512], Clo[B_ * 512];
__device__ __align__(16) u16 Z1hi[B_ * 512], Z1lo[B_ * 512];
__device__ __align__(16) u16 Xhi[B_ * 512],  Xlo[B_ * 512];
__device__ __align__(16) u16 Z2hi[(size_t)T_ * B_ * 512], Z2lo[(size_t)T_ * B_ * 512];
__device__ float g_c[B_ * 512];
__device__ float g_bgp[2048];

// ---------------- helpers ----------------
__device__ __forceinline__ u32 swz(u32 o) { return o ^ ((o >> 3) & 0x70); }
__device__ __forceinline__ u32 s2u(const void* p) {
    u32 a;
    asm("{ .reg .u64 t; cvta.to.shared.u64 t, %1; cvt.u32.u64 %0, t; }" : "=r"(a) : "l"(p));
    return a;
}
__device__ __forceinline__ void cp16(u32 dst, const void* src) {
    asm volatile("cp.async.cg.shared.global [%0], [%1], 16;" :: "r"(dst), "l"(src));
}
__device__ __forceinline__ void cp_commit() { asm volatile("cp.async.commit_group;" ::: "memory"); }
template <int N> __device__ __forceinline__ void cp_wait() {
    asm volatile("cp.async.wait_group %0;" :: "n"(N) : "memory");
}
__device__ __forceinline__ void ldsm4(u32* r, u32 a) {
    asm volatile("ldmatrix.sync.aligned.m8n8.x4.shared.b16 {%0,%1,%2,%3}, [%4];"
                 : "=r"(r[0]), "=r"(r[1]), "=r"(r[2]), "=r"(r[3]) : "r"(a));
}
__device__ __forceinline__ void hmma(float* c, const u32* a, u32 b0, u32 b1) {
    asm volatile("mma.sync.aligned.m16n8k16.row.col.f32.bf16.bf16.f32 "
                 "{%0,%1,%2,%3}, {%4,%5,%6,%7}, {%8,%9}, {%0,%1,%2,%3};"
                 : "+f"(c[0]), "+f"(c[1]), "+f"(c[2]), "+f"(c[3])
                 : "r"(a[0]), "r"(a[1]), "r"(a[2]), "r"(a[3]), "r"(b0), "r"(b1));
}
__device__ __forceinline__ void split1(float v, u16& h, u16& l) {
    __nv_bfloat16 hb = __float2bfloat16(v);
    __nv_bfloat16 lb = __float2bfloat16(v - __bfloat162float(hb));
    h = __bfloat16_as_ushort(hb);
    l = __bfloat16_as_ushort(lb);
}
__device__ __forceinline__ void split2(float a, float b, u32& hi, u32& lo) {
    u16 ah, al, bh, bl;
    split1(a, ah, al); split1(b, bh, bl);
    hi = (u32)ah | ((u32)bh << 16);
    lo = (u32)al | ((u32)bl << 16);
}
__device__ __forceinline__ float sigf(float x) { return 1.f / (1.f + expf(-x)); }

// ---------------- prep: split weights, biases, zero state ----------------
__global__ __launch_bounds__(256) void prep_w(
    const float* __restrict__ W1, const float* __restrict__ W3,
    const float* __restrict__ Wih, const float* __restrict__ Whh,
    const float* __restrict__ bih, const float* __restrict__ bhh)
{
    const int N1 = 524288, N2 = 1048576, N3 = N2 + 2097152;
    const int N4 = N3 + 2048, N5 = N4 + 1048576, N6 = N5 + 524288;
    for (int idx = blockIdx.x * blockDim.x + threadIdx.x; idx < N6;
         idx += gridDim.x * blockDim.x) {
        if (idx < N2) {
            int j = (idx < N1) ? idx : idx - N1;
            float v = (idx < N1) ? W1[j] : W3[j];
            u16 h, l; split1(v, h, l);
            if (idx < N1) { W1hi[j] = h; W1lo[j] = l; }
            else          { W3hi[j] = h; W3lo[j] = l; }
        } else if (idx < N3) {
            int j = idx - N2;
            int p = j >> 10, k = j & 1023;
            int r = (p & 3) * 512 + (p >> 2);          // gate q major in original
            float v = (k < 512) ? Wih[r * 512 + k] : Whh[r * 512 + (k - 512)];
            u16 h, l; split1(v, h, l);
            Wghi[j] = h; Wglo[j] = l;
        } else if (idx < N4) {
            int p = idx - N3, i = p >> 2, q = p & 3;
            g_bgp[p] = bih[q * 512 + i] + bhh[q * 512 + i];
        } else if (idx < N5) {
            int j = idx - N4;
            int sel = j >> 18, w = j & 262143;
            u16* b = (sel == 0) ? Hhi[0] : (sel == 1) ? Hlo[0] : (sel == 2) ? Chi : Clo;
            *(u32*)&b[w * 2] = 0u;
        } else g_c[idx - N5] = 0.f;
    }
}

// ---------------- prep: z2 for all t ----------------
__global__ __launch_bounds__(256) void prep_z2(
    const float* __restrict__ sv, const float* __restrict__ W2, const float* __restrict__ b2)
{
    __shared__ float W2s[10 * 512];
    __shared__ float svs[32 * 10];
    int tid = threadIdx.x;
    for (int idx = tid; idx < 5120; idx += 256)
        W2s[(idx % 10) * 512 + idx / 10] = W2[idx];
    int u0 = blockIdx.x * 32;
    for (int idx = tid; idx < 320; idx += 256) svs[idx] = sv[u0 * 10 + idx];
    __syncthreads();
    int f0 = tid * 2;
    float c0 = b2[f0], c1 = b2[f0 + 1];
    for (int p = 0; p < 32; ++p) {
        int u = u0 + p, bb = u >> 7, tt = u & 127;
        float a0 = c0, a1 = c1;
#pragma unroll
        for (int j = 0; j < 10; ++j) {
            float s = svs[p * 10 + j];
            a0 += s * W2s[j * 512 + f0];
            a1 += s * W2s[j * 512 + f0 + 1];
        }
        u32 hi, lo; split2(fmaxf(a0, 0.f), fmaxf(a1, 0.f), hi, lo);
        size_t off = (size_t)tt * 524288 + (size_t)bb * 512 + f0;
        *(u32*)&Z2hi[off] = hi;
        *(u32*)&Z2lo[off] = lo;
    }
}

// ---------------- fused bf16-split HMMA GEMM ----------------
// MODE 0: z1 = relu([h|c] @ W1^T + b1)      tiles 64x64,  grid (16,8)
// MODE 1: x  = relu([z1|z2_t] @ W3^T + b3)  tiles 64x64,  grid (16,8)
// MODE 2: gates(interleaved) + LSTM cell    tiles 128x64, grid (8,32)
template <int MODE>
__global__ __launch_bounds__(256, 1) void gemm_mma(
    int ping, int t, const float* __restrict__ bias, float* __restrict__ out)
{
    constexpr int MT  = (MODE == 2) ? 128 : 64;
    constexpr int WMW = MT / 32;            // warps along m
    constexpr int WNW = 8 / WMW;            // warps along n
    constexpr int NFR = 8 / WNW;            // n8-fragments per warp
    constexpr int AH = 0, AL = MT * 128, BH = MT * 256, BL = MT * 256 + 8192;
    constexpr int STAGE = MT * 256 + 16384;

    extern __shared__ __align__(16) unsigned char smem[];
    const u32 sb = s2u(smem);
    const int tid = threadIdx.x, lane = tid & 31, wid = tid >> 5;
    const int m0 = blockIdx.x * MT, n0 = blockIdx.y * 64;
    const int wm = wid % WMW, wn = wid / WMW;

    const u16 *A1h, *A1l, *A2h, *A2l, *Wh, *Wl;
    if (MODE == 0) { A1h = Hhi[ping]; A1l = Hlo[ping]; A2h = Chi; A2l = Clo; Wh = W1hi; Wl = W1lo; }
    else if (MODE == 1) {
        size_t zo = (size_t)t * 524288;
        A1h = Z1hi; A1l = Z1lo; A2h = Z2hi + zo; A2l = Z2lo + zo; Wh = W3hi; Wl = W3lo;
    } else { A1h = Xhi; A1l = Xlo; A2h = Hhi[ping]; A2l = Hlo[ping]; Wh = Wghi; Wl = Wglo; }

    float acc[2][NFR][4];
#pragma unroll
    for (int a = 0; a < 2; ++a)
#pragma unroll
        for (int b = 0; b < NFR; ++b)
#pragma unroll
            for (int q = 0; q < 4; ++q) acc[a][b][q] = 0.f;

    // ---- stage loader ----
    auto load_stage = [&](int s) {
        int buf = s & 1, ks = s * 64, kc = ks & 511;
        const u16* sh = (ks < 512) ? A1h : A2h;
        const u16* sl = (ks < 512) ? A1l : A2l;
        u32 base = sb + buf * STAGE;
#pragma unroll
        for (int i = tid; i < MT * 8; i += 256) {
            int row = i >> 3, c16 = i & 7;
            size_t g = (size_t)(m0 + row) * 512 + kc + c16 * 8;
            u32 d = swz((u32)(row * 128 + c16 * 16));
            cp16(base + AH + d, sh + g);
            cp16(base + AL + d, sl + g);
        }
#pragma unroll
        for (int i = tid; i < 512; i += 256) {
            int row = i >> 3, c16 = i & 7;
            size_t g = (size_t)(n0 + row) * 1024 + ks + c16 * 8;
            u32 d = swz((u32)(row * 128 + c16 * 16));
            cp16(base + BH + d, Wh + g);
            cp16(base + BL + d, Wl + g);
        }
    };

    load_stage(0);
    cp_commit();

    const int arow = wm * 32 + (lane & 15);
    const int brow = wn * (NFR * 8) + (lane & 15);
    const int hi16 = (lane >> 4) * 16;

    for (int s = 0; s < 16; ++s) {
        if (s < 15) { load_stage(s + 1); cp_commit(); cp_wait<1>(); }
        else cp_wait<0>();
        __syncthreads();
        u32 base = sb + (s & 1) * STAGE;
#pragma unroll
        for (int kk = 0; kk < 4; ++kk) {
            int kb = kk * 32 + hi16;
            u32 Ahr[2][4], Alr[2][4], Bhr[NFR / 2][4], Blr[NFR / 2][4];
#pragma unroll
            for (int fm = 0; fm < 2; ++fm) {
                u32 off = swz((u32)((arow + fm * 16) * 128 + kb));
                ldsm4(Ahr[fm], base + AH + off);
                ldsm4(Alr[fm], base + AL + off);
            }
#pragma unroll
            for (int nf = 0; nf < NFR / 2; ++nf) {
                u32 off = swz((u32)((brow + nf * 16) * 128 + kb));
                ldsm4(Bhr[nf], base + BH + off);
                ldsm4(Blr[nf], base + BL + off);
            }
#pragma unroll
            for (int fm = 0; fm < 2; ++fm)
#pragma unroll
                for (int fn = 0; fn < NFR; ++fn) {
                    u32 bh0 = Bhr[fn >> 1][fn & 1], bh1 = Bhr[fn >> 1][(fn & 1) + 2];
                    u32 bl0 = Blr[fn >> 1][fn & 1], bl1 = Blr[fn >> 1][(fn & 1) + 2];
                    hmma(acc[fm][fn], Ahr[fm], bh0, bh1);
                    hmma(acc[fm][fn], Ahr[fm], bl0, bl1);
                    hmma(acc[fm][fn], Alr[fm], bh0, bh1);
                }
        }
        __syncthreads();
    }

    // ---------------- epilogue ----------------
    if (MODE < 2) {
        u16* Dh = (MODE == 0) ? Z1hi : Xhi;
        u16* Dl = (MODE == 0) ? Z1lo : Xlo;
#pragma unroll
        for (int fm = 0; fm < 2; ++fm)
#pragma unroll
            for (int fn = 0; fn < NFR; ++fn) {
                int c = n0 + wn * (NFR * 8) + fn * 8 + (lane & 3) * 2;
                int r = m0 + wm * 32 + fm * 16 + (lane >> 2);
                float b0 = bias[c], b1v = bias[c + 1];
                u32 hi, lo;
                split2(fmaxf(acc[fm][fn][0] + b0, 0.f), fmaxf(acc[fm][fn][1] + b1v, 0.f), hi, lo);
                *(u32*)&Dh[(size_t)r * 512 + c] = hi;
                *(u32*)&Dl[(size_t)r * 512 + c] = lo;
                split2(fmaxf(acc[fm][fn][2] + b0, 0.f), fmaxf(acc[fm][fn][3] + b1v, 0.f), hi, lo);
                *(u32*)&Dh[(size_t)(r + 8) * 512 + c] = hi;
                *(u32*)&Dl[(size_t)(r + 8) * 512 + c] = lo;
            }
    } else {
        u16* hh = Hhi[ping ^ 1];
        u16* hl = Hlo[ping ^ 1];
        bool odd = lane & 1;
#pragma unroll
        for (int fm = 0; fm < 2; ++fm)
#pragma unroll
            for (int fn = 0; fn < NFR; ++fn) {
                float v0 = acc[fm][fn][0], v1 = acc[fm][fn][1];
                float v2 = acc[fm][fn][2], v3 = acc[fm][fn][3];
                float s0 = __shfl_xor_sync(0xFFFFFFFFu, v0, 1);
                float s1 = __shfl_xor_sync(0xFFFFFFFFu, v1, 1);
                float s2 = __shfl_xor_sync(0xFFFFFFFFu, v2, 1);
                float s3 = __shfl_xor_sync(0xFFFFFFFFu, v3, 1);
                int p = n0 + wn * (NFR * 8) + fn * 8 + (lane & 3) * 2;
                int u = p >> 2;
                int row = m0 + wm * 32 + fm * 16 + (lane >> 2) + (odd ? 8 : 0);
                float gi = odd ? s2 : v0;
                float gf = odd ? s3 : v1;
                float gg = odd ? v2 : s0;
                float go = odd ? v3 : s1;
                int pb = u * 4;
                gi += g_bgp[pb];     gf += g_bgp[pb + 1];
                gg += g_bgp[pb + 2]; go += g_bgp[pb + 3];
                float I = sigf(gi), F = sigf(gf), G = tanhf(gg), O = sigf(go);
                size_t ix = (size_t)row * 512 + u;
                float cn = F * g_c[ix] + I * G;
                float hn = O * tanhf(cn);
                g_c[ix] = cn;
                out[((size_t)row * T_ + t) * 512 + u] = hn;
                u16 hH, hL, cH, cL;
                split1(hn, hH, hL);
                split1(cn, cH, cL);
                hh[ix] = hH; hl[ix] = hL;
                Chi[ix] = cH; Clo[ix] = cL;
            }
    }
}

// ---------------- launch ----------------
extern "C" void kernel_launch(void* const* d_in, const int* in_sizes, int n_in,
                              void* d_out, int out_size)
{
    const float* sv  = (const float*)d_in[0];
    const float* W1  = (const float*)d_in[1];
    const float* b1  = (const float*)d_in[2];
    const float* W2  = (const float*)d_in[3];
    const float* b2  = (const float*)d_in[4];
    const float* W3  = (const float*)d_in[5];
    const float* b3  = (const float*)d_in[6];
    const float* Wih = (const float*)d_in[7];
    const float* Whh = (const float*)d_in[8];
    const float* bih = (const float*)d_in[9];
    const float* bhh = (const float*)d_in[10];
    float* out = (float*)d_out;

    const int SM64  = 2 * (64 * 256 + 16384);    // 65536
    const int SM128 = 2 * (128 * 256 + 16384);   // 98304
    cudaFuncSetAttribute(gemm_mma<0>, cudaFuncAttributeMaxDynamicSharedMemorySize, SM64);
    cudaFuncSetAttribute(gemm_mma<1>, cudaFuncAttributeMaxDynamicSharedMemorySize, SM64);
    cudaFuncSetAttribute(gemm_mma<2>, cudaFuncAttributeMaxDynamicSharedMemorySize, SM128);

    prep_w<<<2048, 256>>>(W1, W3, Wih, Whh, bih, bhh);
    prep_z2<<<4096, 256>>>(sv, W2, b2);

    dim3 gs(16, 8), gg(8, 32);
    for (int t = 0; t < T_; ++t) {
        int ping = t & 1;
        gemm_mma<0><<<gs, 256, SM64>>>(ping, t, b1, out);
        gemm_mma<1><<<gs, 256, SM64>>>(ping, t, b3, out);
        gemm_mma<2><<<gg, 256, SM128>>>(ping, t, nullptr, out);
    }
}

// round 6
// speedup vs baseline: 2.2776x; 1.0183x over previous
#include <cuda_runtime.h>
#include <cuda_bf16.h>
#include <cstdint>

#define B_ 1024
#define T_ 128

typedef unsigned short u16;
typedef uint32_t u32;

// ---------------- static device buffers (plain row-major, k-contiguous) ----------------
__device__ __align__(16) u16 W1hi[512 * 1024], W1lo[512 * 1024];   // [n][k]
__device__ __align__(16) u16 W3hi[512 * 1024], W3lo[512 * 1024];
__device__ __align__(16) u16 Wghi[2048 * 1024], Wglo[2048 * 1024]; // [p=4i+q][k over x|h]
__device__ __align__(16) u16 Hhi[2][B_ * 512], Hlo[2][B_ * 512];
__device__ __align__(16) u16 Chi[B_ * 512], Clo[B_ * 512];
__device__ __align__(16) u16 Z1hi[B_ * 512], Z1lo[B_ * 512];
__device__ __align__(16) u16 Xhi[B_ * 512],  Xlo[B_ * 512];
__device__ __align__(16) u16 Z2hi[(size_t)T_ * B_ * 512], Z2lo[(size_t)T_ * B_ * 512];
__device__ float g_c[B_ * 512];
__device__ float g_bgp[2048];

// ---------------- helpers ----------------
__device__ __forceinline__ u32 swz(u32 o) { return o ^ ((o >> 3) & 0x70); }
__device__ __forceinline__ u32 s2u(const void* p) {
    u32 a;
    asm("{ .reg .u64 t; cvta.to.shared.u64 t, %1; cvt.u32.u64 %0, t; }" : "=r"(a) : "l"(p));
    return a;
}
__device__ __forceinline__ void cp16(u32 dst, const void* src) {
    asm volatile("cp.async.cg.shared.global [%0], [%1], 16;" :: "r"(dst), "l"(src));
}
__device__ __forceinline__ void cp_commit() { asm volatile("cp.async.commit_group;" ::: "memory"); }
template <int N> __device__ __forceinline__ void cp_wait() {
    asm volatile("cp.async.wait_group %0;" :: "n"(N) : "memory");
}
__device__ __forceinline__ void ldsm4(u32* r, u32 a) {
    asm volatile("ldmatrix.sync.aligned.m8n8.x4.shared.b16 {%0,%1,%2,%3}, [%4];"
                 : "=r"(r[0]), "=r"(r[1]), "=r"(r[2]), "=r"(r[3]) : "r"(a));
}
__device__ __forceinline__ void hmma(float* c, const u32* a, u32 b0, u32 b1) {
    asm volatile("mma.sync.aligned.m16n8k16.row.col.f32.bf16.bf16.f32 "
                 "{%0,%1,%2,%3}, {%4,%5,%6,%7}, {%8,%9}, {%0,%1,%2,%3};"
                 : "+f"(c[0]), "+f"(c[1]), "+f"(c[2]), "+f"(c[3])
                 : "r"(a[0]), "r"(a[1]), "r"(a[2]), "r"(a[3]), "r"(b0), "r"(b1));
}
__device__ __forceinline__ void split1(float v, u16& h, u16& l) {
    __nv_bfloat16 hb = __float2bfloat16(v);
    __nv_bfloat16 lb = __float2bfloat16(v - __bfloat162float(hb));
    h = __bfloat16_as_ushort(hb);
    l = __bfloat16_as_ushort(lb);
}
__device__ __forceinline__ void split2(float a, float b, u32& hi, u32& lo) {
    u16 ah, al, bh, bl;
    split1(a, ah, al); split1(b, bh, bl);
    hi = (u32)ah | ((u32)bh << 16);
    lo = (u32)al | ((u32)bl << 16);
}
__device__ __forceinline__ float sigf(float x) { return 1.f / (1.f + expf(-x)); }

// ---------------- prep: split weights, biases, zero state ----------------
__global__ __launch_bounds__(256) void prep_w(
    const float* __restrict__ W1, const float* __restrict__ W3,
    const float* __restrict__ Wih, const float* __restrict__ Whh,
    const float* __restrict__ bih, const float* __restrict__ bhh)
{
    const int N1 = 524288, N2 = 1048576, N3 = N2 + 2097152;
    const int N4 = N3 + 2048, N5 = N4 + 1048576, N6 = N5 + 524288;
    for (int idx = blockIdx.x * blockDim.x + threadIdx.x; idx < N6;
         idx += gridDim.x * blockDim.x) {
        if (idx < N2) {
            int j = (idx < N1) ? idx : idx - N1;
            float v = (idx < N1) ? W1[j] : W3[j];
            u16 h, l; split1(v, h, l);
            if (idx < N1) { W1hi[j] = h; W1lo[j] = l; }
            else          { W3hi[j] = h; W3lo[j] = l; }
        } else if (idx < N3) {
            int j = idx - N2;
            int p = j >> 10, k = j & 1023;
            int r = (p & 3) * 512 + (p >> 2);
            float v = (k < 512) ? Wih[r * 512 + k] : Whh[r * 512 + (k - 512)];
            u16 h, l; split1(v, h, l);
            Wghi[j] = h; Wglo[j] = l;
        } else if (idx < N4) {
            int p = idx - N3, i = p >> 2, q = p & 3;
            g_bgp[p] = bih[q * 512 + i] + bhh[q * 512 + i];
        } else if (idx < N5) {
            int j = idx - N4;
            int sel = j >> 18, w = j & 262143;
            u16* b = (sel == 0) ? Hhi[0] : (sel == 1) ? Hlo[0] : (sel == 2) ? Chi : Clo;
            *(u32*)&b[w * 2] = 0u;
        } else g_c[idx - N5] = 0.f;
    }
}

// ---------------- prep: z2 for all t ----------------
__global__ __launch_bounds__(256) void prep_z2(
    const float* __restrict__ sv, const float* __restrict__ W2, const float* __restrict__ b2)
{
    __shared__ float W2s[10 * 512];
    __shared__ float svs[32 * 10];
    int tid = threadIdx.x;
    for (int idx = tid; idx < 5120; idx += 256)
        W2s[(idx % 10) * 512 + idx / 10] = W2[idx];
    int u0 = blockIdx.x * 32;
    for (int idx = tid; idx < 320; idx += 256) svs[idx] = sv[u0 * 10 + idx];
    __syncthreads();
    int f0 = tid * 2;
    float c0 = b2[f0], c1 = b2[f0 + 1];
    for (int p = 0; p < 32; ++p) {
        int u = u0 + p, bb = u >> 7, tt = u & 127;
        float a0 = c0, a1 = c1;
#pragma unroll
        for (int j = 0; j < 10; ++j) {
            float s = svs[p * 10 + j];
            a0 += s * W2s[j * 512 + f0];
            a1 += s * W2s[j * 512 + f0 + 1];
        }
        u32 hi, lo; split2(fmaxf(a0, 0.f), fmaxf(a1, 0.f), hi, lo);
        size_t off = (size_t)tt * 524288 + (size_t)bb * 512 + f0;
        *(u32*)&Z2hi[off] = hi;
        *(u32*)&Z2lo[off] = lo;
    }
}

// ---------------- fused bf16-split HMMA GEMM ----------------
// MODE 0: z1 = relu([h|c] @ W1^T + b1)      tile 32x64, 128thr, grid (32,8)=256
// MODE 1: x  = relu([z1|z2_t] @ W3^T + b3)  tile 32x64, 128thr, grid (32,8)=256
// MODE 2: gates(interleaved) + LSTM cell    tile 128x64, 256thr, grid (8,32)=256
template <int MODE>
__global__ __launch_bounds__((MODE == 2) ? 256 : 128, 1) void gemm_mma(
    int ping, int t, const float* __restrict__ bias, float* __restrict__ out)
{
    constexpr int MT  = (MODE == 2) ? 128 : 32;
    constexpr int TH  = (MODE == 2) ? 256 : 128;
    constexpr int NWARP = TH / 32;
    constexpr int WMW = MT / 32 < NWARP ? ((MODE == 2) ? 4 : 1) : NWARP;
    constexpr int WNW = NWARP / WMW;
    constexpr int NFR = 8 / WNW;
    constexpr int NSTAGE = (MODE == 2) ? 2 : 3;
    constexpr int AH = 0, AL = MT * 128, BH = MT * 256, BL = MT * 256 + 8192;
    constexpr int STAGE = MT * 256 + 16384;

    extern __shared__ __align__(16) unsigned char smem[];
    const u32 sb = s2u(smem);
    const int tid = threadIdx.x, lane = tid & 31, wid = tid >> 5;
    const int m0 = blockIdx.x * MT, n0 = blockIdx.y * 64;
    const int wm = wid % WMW, wn = wid / WMW;

    const u16 *A1h, *A1l, *A2h, *A2l, *Wh, *Wl;
    if (MODE == 0) { A1h = Hhi[ping]; A1l = Hlo[ping]; A2h = Chi; A2l = Clo; Wh = W1hi; Wl = W1lo; }
    else if (MODE == 1) {
        size_t zo = (size_t)t * 524288;
        A1h = Z1hi; A1l = Z1lo; A2h = Z2hi + zo; A2l = Z2lo + zo; Wh = W3hi; Wl = W3lo;
    } else { A1h = Xhi; A1l = Xlo; A2h = Hhi[ping]; A2l = Hlo[ping]; Wh = Wghi; Wl = Wglo; }

    float acc[2][NFR][4];
#pragma unroll
    for (int a = 0; a < 2; ++a)
#pragma unroll
        for (int b = 0; b < NFR; ++b)
#pragma unroll
            for (int q = 0; q < 4; ++q) acc[a][b][q] = 0.f;

    auto load_stage = [&](int s) {
        int buf = s % NSTAGE, ks = s * 64, kc = ks & 511;
        const u16* sh = (ks < 512) ? A1h : A2h;
        const u16* sl = (ks < 512) ? A1l : A2l;
        u32 base = sb + buf * STAGE;
#pragma unroll
        for (int i = tid; i < MT * 8; i += TH) {
            int row = i >> 3, c16 = i & 7;
            size_t g = (size_t)(m0 + row) * 512 + kc + c16 * 8;
            u32 d = swz((u32)(row * 128 + c16 * 16));
            cp16(base + AH + d, sh + g);
            cp16(base + AL + d, sl + g);
        }
#pragma unroll
        for (int i = tid; i < 512; i += TH) {
            int row = i >> 3, c16 = i & 7;
            size_t g = (size_t)(n0 + row) * 1024 + ks + c16 * 8;
            u32 d = swz((u32)(row * 128 + c16 * 16));
            cp16(base + BH + d, Wh + g);
            cp16(base + BL + d, Wl + g);
        }
    };

#pragma unroll
    for (int s = 0; s < NSTAGE - 1; ++s) { load_stage(s); cp_commit(); }

    const int arow = wm * 32 + (lane & 15);
    const int brow = wn * (NFR * 8) + (lane & 15);
    const u32 hi16 = (u32)((lane >> 4) * 16);

    for (int s = 0; s < 16; ++s) {
        cp_wait<NSTAGE - 2>();
        __syncthreads();
        if (s + NSTAGE - 1 < 16) { load_stage(s + NSTAGE - 1); cp_commit(); }
        u32 base = sb + (u32)(s % NSTAGE) * STAGE;

        if (MODE == 2) {
#pragma unroll
            for (int kk = 0; kk < 4; ++kk) {
                u32 kb = (u32)(kk * 32) + hi16;
                u32 Ahr[2][4], Alr[2][4], Bhr[2][4], Blr[2][4];
#pragma unroll
                for (int fm = 0; fm < 2; ++fm) {
                    u32 off = swz((u32)((arow + fm * 16) * 128) + kb);
                    ldsm4(Ahr[fm], base + AH + off);
                    ldsm4(Alr[fm], base + AL + off);
                }
#pragma unroll
                for (int nf = 0; nf < 2; ++nf) {
                    u32 off = swz((u32)((brow + nf * 16) * 128) + kb);
                    ldsm4(Bhr[nf], base + BH + off);
                    ldsm4(Blr[nf], base + BL + off);
                }
#pragma unroll
                for (int fm = 0; fm < 2; ++fm)
#pragma unroll
                    for (int fn = 0; fn < 4; ++fn) {
                        u32 b0 = Bhr[fn >> 1][fn & 1], b1 = Bhr[fn >> 1][(fn & 1) + 2];
                        u32 l0 = Blr[fn >> 1][fn & 1], l1 = Blr[fn >> 1][(fn & 1) + 2];
                        hmma(acc[fm][fn], Ahr[fm], b0, b1);
                        hmma(acc[fm][fn], Ahr[fm], l0, l1);
                        hmma(acc[fm][fn], Alr[fm], b0, b1);
                    }
            }
        } else {
            u32 Ahf[2][2][4], Alf[2][2][4], Bhf[2][4], Blf[2][4];
#define LDFRAG(bf, kk) do { \
            u32 kb = (u32)((kk) * 32) + hi16; \
            ldsm4(Ahf[bf][0], base + AH + swz((u32)(arow * 128) + kb)); \
            ldsm4(Ahf[bf][1], base + AH + swz((u32)((arow + 16) * 128) + kb)); \
            ldsm4(Alf[bf][0], base + AL + swz((u32)(arow * 128) + kb)); \
            ldsm4(Alf[bf][1], base + AL + swz((u32)((arow + 16) * 128) + kb)); \
            ldsm4(Bhf[bf], base + BH + swz((u32)(brow * 128) + kb)); \
            ldsm4(Blf[bf], base + BL + swz((u32)(brow * 128) + kb)); \
        } while (0)
            LDFRAG(0, 0);
#pragma unroll
            for (int kk = 0; kk < 4; ++kk) {
                const int cur = kk & 1;
                if (kk < 3) LDFRAG(cur ^ 1, kk + 1);
#pragma unroll
                for (int fm = 0; fm < 2; ++fm)
#pragma unroll
                    for (int fn = 0; fn < 2; ++fn) {
                        u32 b0 = Bhf[cur][fn], b1 = Bhf[cur][fn + 2];
                        u32 l0 = Blf[cur][fn], l1 = Blf[cur][fn + 2];
                        hmma(acc[fm][fn], Ahf[cur][fm], b0, b1);
                        hmma(acc[fm][fn], Ahf[cur][fm], l0, l1);
                        hmma(acc[fm][fn], Alf[cur][fm], b0, b1);
                    }
            }
#undef LDFRAG
        }
        __syncthreads();
    }

    // ---------------- epilogue ----------------
    if (MODE < 2) {
        u16* Dh = (MODE == 0) ? Z1hi : Xhi;
        u16* Dl = (MODE == 0) ? Z1lo : Xlo;
#pragma unroll
        for (int fm = 0; fm < 2; ++fm)
#pragma unroll
            for (int fn = 0; fn < NFR; ++fn) {
                int c = n0 + wn * (NFR * 8) + fn * 8 + (lane & 3) * 2;
                int r = m0 + wm * 32 + fm * 16 + (lane >> 2);
                float b0 = bias[c], b1v = bias[c + 1];
                u32 hi, lo;
                split2(fmaxf(acc[fm][fn][0] + b0, 0.f), fmaxf(acc[fm][fn][1] + b1v, 0.f), hi, lo);
                *(u32*)&Dh[(size_t)r * 512 + c] = hi;
                *(u32*)&Dl[(size_t)r * 512 + c] = lo;
                split2(fmaxf(acc[fm][fn][2] + b0, 0.f), fmaxf(acc[fm][fn][3] + b1v, 0.f), hi, lo);
                *(u32*)&Dh[(size_t)(r + 8) * 512 + c] = hi;
                *(u32*)&Dl[(size_t)(r + 8) * 512 + c] = lo;
            }
    } else {
        u16* hh = Hhi[ping ^ 1];
        u16* hl = Hlo[ping ^ 1];
        bool odd = lane & 1;
#pragma unroll
        for (int fm = 0; fm < 2; ++fm)
#pragma unroll
            for (int fn = 0; fn < NFR; ++fn) {
                float v0 = acc[fm][fn][0], v1 = acc[fm][fn][1];
                float v2 = acc[fm][fn][2], v3 = acc[fm][fn][3];
                float s0 = __shfl_xor_sync(0xFFFFFFFFu, v0, 1);
                float s1 = __shfl_xor_sync(0xFFFFFFFFu, v1, 1);
                float s2 = __shfl_xor_sync(0xFFFFFFFFu, v2, 1);
                float s3 = __shfl_xor_sync(0xFFFFFFFFu, v3, 1);
                int p = n0 + wn * (NFR * 8) + fn * 8 + (lane & 3) * 2;
                int u = p >> 2;
                int row = m0 + wm * 32 + fm * 16 + (lane >> 2) + (odd ? 8 : 0);
                float gi = odd ? s2 : v0;
                float gf = odd ? s3 : v1;
                float gg = odd ? v2 : s0;
                float go = odd ? v3 : s1;
                int pb = u * 4;
                gi += g_bgp[pb];     gf += g_bgp[pb + 1];
                gg += g_bgp[pb + 2]; go += g_bgp[pb + 3];
                float I = sigf(gi), F = sigf(gf), G = tanhf(gg), O = sigf(go);
                size_t ix = (size_t)row * 512 + u;
                float cn = F * g_c[ix] + I * G;
                float hn = O * tanhf(cn);
                g_c[ix] = cn;
                out[((size_t)row * T_ + t) * 512 + u] = hn;
                u16 hH, hL, cH, cL;
                split1(hn, hH, hL);
                split1(cn, cH, cL);
                hh[ix] = hH; hl[ix] = hL;
                Chi[ix] = cH; Clo[ix] = cL;
            }
    }
}

// ---------------- launch ----------------
extern "C" void kernel_launch(void* const* d_in, const int* in_sizes, int n_in,
                              void* d_out, int out_size)
{
    const float* sv  = (const float*)d_in[0];
    const float* W1  = (const float*)d_in[1];
    const float* b1  = (const float*)d_in[2];
    const float* W2  = (const float*)d_in[3];
    const float* b2  = (const float*)d_in[4];
    const float* W3  = (const float*)d_in[5];
    const float* b3  = (const float*)d_in[6];
    const float* Wih = (const float*)d_in[7];
    const float* Whh = (const float*)d_in[8];
    const float* bih = (const float*)d_in[9];
    const float* bhh = (const float*)d_in[10];
    float* out = (float*)d_out;

    const int SM01 = 3 * (32 * 256 + 16384);     // 73728
    const int SM2  = 2 * (128 * 256 + 16384);    // 98304
    cudaFuncSetAttribute(gemm_mma<0>, cudaFuncAttributeMaxDynamicSharedMemorySize, SM01);
    cudaFuncSetAttribute(gemm_mma<1>, cudaFuncAttributeMaxDynamicSharedMemorySize, SM01);
    cudaFuncSetAttribute(gemm_mma<2>, cudaFuncAttributeMaxDynamicSharedMemorySize, SM2);

    prep_w<<<2048, 256>>>(W1, W3, Wih, Whh, bih, bhh);
    prep_z2<<<4096, 256>>>(sv, W2, b2);

    dim3 gs(32, 8), gg(8, 32);
    for (int t = 0; t < T_; ++t) {
        int ping = t & 1;
        gemm_mma<0><<<gs, 128, SM01>>>(ping, t, b1, out);
        gemm_mma<1><<<gs, 128, SM01>>>(ping, t, b3, out);
        gemm_mma<2><<<gg, 256, SM2>>>(ping, t, nullptr, out);
    }
}